// round 16
// baseline (speedup 1.0000x reference)
#include <cuda_runtime.h>
#include <cuda_fp16.h>
#include <cstdint>

// Problem-size caps (fixed by the dataset)
#define MAXN 100000
#define MAXE 1600000
#define DFEAT 48
#define NI4   6           // int4 (8 fp16) per node row: 48 halfs = 96 B
#define KITER 10
#define ALPHA 0.1f

// ---------------- scratch (static device memory; no allocations) -------------
__device__ int  g_is64;
__device__ int  g_deg[MAXN];
__device__ int  g_off[MAXN + 1];
__device__ int  g_bsums[256];
__device__ int  g_slot[MAXE];
__device__ int2 g_edge[MAXE];                 // (col, raw-w bits), row-sorted
__device__ int4 g_xh[(size_t)MAXN * NI4];     // x in fp16 rows
__device__ int4 g_hh0[(size_t)MAXN * NI4];    // ping
__device__ int4 g_hh1[(size_t)MAXN * NI4];    // pong

// ---------------- precompute kernels ----------------------------------------

// Detect int64 vs int32 edge_index: int64 (values < 2^31) has every odd 32-bit
// word zero; int32 data has random indices there.
__global__ void k_detect(const int* __restrict__ ei32, int E) {
    __shared__ int any;
    if (threadIdx.x == 0) any = 0;
    __syncthreads();
    int nchk = 1024; if (nchk > E) nchk = E;
    for (int i = threadIdx.x; i < nchk; i += blockDim.x)
        if (ei32[2 * i + 1] != 0) any = 1;
    __syncthreads();
    if (threadIdx.x == 0) g_is64 = (any == 0) ? 1 : 0;
}

__global__ void k_zero(int* deg, int n) {
    int i = blockIdx.x * blockDim.x + threadIdx.x;
    if (i < n) deg[i] = 0;
}

// x (fp32) -> fp16 rows (int4-packed). i over N*NI4 int4 units.
__global__ void k_xhalf(const float4* __restrict__ x4, int4* __restrict__ xh, int n4) {
    int i = blockIdx.x * blockDim.x + threadIdx.x;
    if (i >= n4) return;
    float4 a = __ldg(&x4[2 * i]);
    float4 b = __ldg(&x4[2 * i + 1]);
    __half2 h0 = __floats2half2_rn(a.x, a.y);
    __half2 h1 = __floats2half2_rn(a.z, a.w);
    __half2 h2 = __floats2half2_rn(b.x, b.y);
    __half2 h3 = __floats2half2_rn(b.z, b.w);
    int4 v;
    v.x = *(int*)&h0; v.y = *(int*)&h1; v.z = *(int*)&h2; v.w = *(int*)&h3;
    xh[i] = v;
}

// Degree count + per-row slot per edge. 8 edges/thread, vector index loads
// (MLP to hide atomic-return + DRAM latency).
__global__ void k_narrow(const void* __restrict__ ei,
                         int* __restrict__ deg, int* __restrict__ slot,
                         int E, int N) {
    int base = (blockIdx.x * blockDim.x + threadIdx.x) * 8;
    if (base >= E) return;
    int r[8];
    if (base + 8 <= E) {
        if (g_is64) {
            const longlong2* p = (const longlong2*)ei;
#pragma unroll
            for (int j = 0; j < 4; j++) {
                longlong2 a = __ldg(&p[(base >> 1) + j]);
                r[2 * j] = (int)a.x; r[2 * j + 1] = (int)a.y;
            }
        } else {
            const int4* p = (const int4*)ei;
            int4 a = __ldg(&p[base >> 2]);
            int4 b = __ldg(&p[(base >> 2) + 1]);
            r[0] = a.x; r[1] = a.y; r[2] = a.z; r[3] = a.w;
            r[4] = b.x; r[5] = b.y; r[6] = b.z; r[7] = b.w;
        }
#pragma unroll
        for (int j = 0; j < 8; j++) {
            int rr = r[j];
            if (rr < 0) rr = 0; if (rr >= N) rr = N - 1;  // crash-proofing only
            slot[base + j] = atomicAdd(&deg[rr], 1);
        }
    } else {
        for (int e = base; e < E; e++) {
            int rr = g_is64 ? (int)((const long long*)ei)[e] : ((const int*)ei)[e];
            if (rr < 0) rr = 0; if (rr >= N) rr = N - 1;
            slot[e] = atomicAdd(&deg[rr], 1);
        }
    }
}

// 3-phase exclusive scan of deg -> off
__global__ void k_scan1(const int* __restrict__ deg, int* __restrict__ off,
                        int* __restrict__ bsums, int n) {
    __shared__ int sh[1024];
    int i = blockIdx.x * 1024 + threadIdx.x;
    int v = (i < n) ? deg[i] : 0;
    sh[threadIdx.x] = v;
    __syncthreads();
    for (int d = 1; d < 1024; d <<= 1) {
        int t = 0;
        if (threadIdx.x >= d) t = sh[threadIdx.x - d];
        __syncthreads();
        if (threadIdx.x >= d) sh[threadIdx.x] += t;
        __syncthreads();
    }
    if (i < n) off[i] = sh[threadIdx.x] - v;
    if (threadIdx.x == 1023) bsums[blockIdx.x] = sh[1023];
}

__global__ void k_scan2(int* bsums, int nb) {
    if (threadIdx.x == 0 && blockIdx.x == 0) {
        int acc = 0;
        for (int i = 0; i < nb; i++) { int t = bsums[i]; bsums[i] = acc; acc += t; }
    }
}

__global__ void k_scan3(int* __restrict__ off, const int* __restrict__ bsums,
                        int n, int total) {
    int i = blockIdx.x * 1024 + threadIdx.x;
    if (i < n) off[i] += bsums[blockIdx.x];
    if (i == 0) off[n] = total;
}

// Counting-sort scatter using precomputed slots (no atomics): (col, raw w).
// 4 edges/thread, vector loads for MLP.
__global__ void k_scatter(const void* __restrict__ ei,
                          const int* __restrict__ slot,
                          const float* __restrict__ w,
                          const int* __restrict__ off, int2* __restrict__ ed,
                          int E, int N) {
    int base = (blockIdx.x * blockDim.x + threadIdx.x) * 4;
    if (base >= E) return;
    if (base + 4 <= E) {
        int r[4], c[4];
        if (g_is64) {
            const longlong2* p = (const longlong2*)ei;
            longlong2 a = __ldg(&p[base >> 1]);
            longlong2 b = __ldg(&p[(base >> 1) + 1]);
            r[0] = (int)a.x; r[1] = (int)a.y; r[2] = (int)b.x; r[3] = (int)b.y;
            longlong2 cA = __ldg(&p[(E + base) >> 1]);
            longlong2 cB = __ldg(&p[((E + base) >> 1) + 1]);
            c[0] = (int)cA.x; c[1] = (int)cA.y; c[2] = (int)cB.x; c[3] = (int)cB.y;
        } else {
            const int4* p = (const int4*)ei;
            int4 a = __ldg(&p[base >> 2]);
            int4 cc = __ldg(&p[(E + base) >> 2]);
            r[0] = a.x; r[1] = a.y; r[2] = a.z; r[3] = a.w;
            c[0] = cc.x; c[1] = cc.y; c[2] = cc.z; c[3] = cc.w;
        }
        float4 wv = __ldg((const float4*)(w + base));
        float wa[4] = {wv.x, wv.y, wv.z, wv.w};
        int4 sl = __ldg((const int4*)(slot + base));
        int sa[4] = {sl.x, sl.y, sl.z, sl.w};
#pragma unroll
        for (int j = 0; j < 4; j++) {
            int rr = r[j], cc2 = c[j];
            if (rr < 0) rr = 0; if (rr >= N) rr = N - 1;
            if (cc2 < 0) cc2 = 0; if (cc2 >= N) cc2 = N - 1;
            int p2 = __ldg(&off[rr]) + sa[j];
            ed[p2] = make_int2(cc2, __float_as_int(wa[j]));
        }
    } else {
        for (int e = base; e < E; e++) {
            int rr = g_is64 ? (int)((const long long*)ei)[e] : ((const int*)ei)[e];
            int cc2 = g_is64 ? (int)((const long long*)ei)[(size_t)E + e]
                             : ((const int*)ei)[E + e];
            if (rr < 0) rr = 0; if (rr >= N) rr = N - 1;
            if (cc2 < 0) cc2 = 0; if (cc2 >= N) cc2 = N - 1;
            ed[off[rr] + slot[e]] = make_int2(cc2, __float_as_int(w[e]));
        }
    }
}

// ---------------- propagation mainloop ---------------------------------------
// 8 lanes per destination node; lanes 0-5 each fetch one int4 (8 fp16) of the
// 96-B source row with a single LDG.128 -> ~1.5 L1tex wavefronts/edge instead
// of 3. Accumulate fp32; normalization folded into epilogue: 0.9/(sum_w+1e-10).
template<bool FINAL>
__global__ void __launch_bounds__(256)
k_proph(const int4* __restrict__ hin,
        const int4* __restrict__ xh, const float4* __restrict__ x4,
        int4* __restrict__ hout, float4* __restrict__ fout,
        const int* __restrict__ off, const int2* __restrict__ ed, int n) {
    int gid  = blockIdx.x * blockDim.x + threadIdx.x;
    int node = gid >> 3;
    int lane = gid & 7;
    if (node >= n) return;
    bool act = (lane < 6);

    int s = __ldg(&off[node]);
    int e = __ldg(&off[node + 1]);

    float a0 = 0.f, a1 = 0.f, a2 = 0.f, a3 = 0.f,
          a4 = 0.f, a5 = 0.f, a6 = 0.f, a7 = 0.f;
    float ws = 0.f;
    for (int idx = s; idx < e; idx++) {
        int2 t = __ldg(&ed[idx]);                     // broadcast in 8-lane group
        float ww = __int_as_float(t.y);
        ws += ww;
        if (act) {
            int4 v = __ldg(hin + t.x * NI4 + lane);   // one LDG.128 per lane
            __half2 h0 = *(__half2*)&v.x, h1 = *(__half2*)&v.y;
            __half2 h2 = *(__half2*)&v.z, h3 = *(__half2*)&v.w;
            float2 f0 = __half22float2(h0), f1 = __half22float2(h1);
            float2 f2 = __half22float2(h2), f3 = __half22float2(h3);
            a0 = fmaf(ww, f0.x, a0);  a1 = fmaf(ww, f0.y, a1);
            a2 = fmaf(ww, f1.x, a2);  a3 = fmaf(ww, f1.y, a3);
            a4 = fmaf(ww, f2.x, a4);  a5 = fmaf(ww, f2.y, a5);
            a6 = fmaf(ww, f3.x, a6);  a7 = fmaf(ww, f3.y, a7);
        }
    }

    float sc = (1.0f - ALPHA) / (ws + 1e-10f);
    if (!act) return;

    int o = node * NI4 + lane;
    if (FINAL) {
        // fp32 x, fp32 out: lane owns floats [8*lane, 8*lane+8) of the 48-row
        int fo = node * (DFEAT / 4) + lane * 2;
        float4 xa = __ldg(x4 + fo);
        float4 xb = __ldg(x4 + fo + 1);
        float4 ra = make_float4(fmaf(sc, a0, ALPHA * xa.x), fmaf(sc, a1, ALPHA * xa.y),
                                fmaf(sc, a2, ALPHA * xa.z), fmaf(sc, a3, ALPHA * xa.w));
        float4 rb = make_float4(fmaf(sc, a4, ALPHA * xb.x), fmaf(sc, a5, ALPHA * xb.y),
                                fmaf(sc, a6, ALPHA * xb.z), fmaf(sc, a7, ALPHA * xb.w));
        fout[fo]     = ra;
        fout[fo + 1] = rb;
    } else {
        int4 xv = __ldg(xh + o);
        __half2 x0 = *(__half2*)&xv.x, x1 = *(__half2*)&xv.y;
        __half2 x2h = *(__half2*)&xv.z, x3 = *(__half2*)&xv.w;
        float2 g0 = __half22float2(x0), g1 = __half22float2(x1);
        float2 g2 = __half22float2(x2h), g3 = __half22float2(x3);
        __half2 r0 = __floats2half2_rn(fmaf(sc, a0, ALPHA * g0.x), fmaf(sc, a1, ALPHA * g0.y));
        __half2 r1 = __floats2half2_rn(fmaf(sc, a2, ALPHA * g1.x), fmaf(sc, a3, ALPHA * g1.y));
        __half2 r2 = __floats2half2_rn(fmaf(sc, a4, ALPHA * g2.x), fmaf(sc, a5, ALPHA * g2.y));
        __half2 r3 = __floats2half2_rn(fmaf(sc, a6, ALPHA * g3.x), fmaf(sc, a7, ALPHA * g3.y));
        int4 out;
        out.x = *(int*)&r0; out.y = *(int*)&r1; out.z = *(int*)&r2; out.w = *(int*)&r3;
        hout[o] = out;
    }
}

// ---------------- launcher ----------------------------------------------------
extern "C" void kernel_launch(void* const* d_in, const int* in_sizes, int n_in,
                              void* d_out, int out_size) {
    const float* x  = (const float*)d_in[0];
    const void*  ei = d_in[1];
    const float* ew = (const float*)d_in[2];

    int N = in_sizes[0] / DFEAT;
    int E = in_sizes[2];
    if (N > MAXN) N = MAXN;
    if (E > MAXE) E = MAXE;

    int *deg, *off, *bsums, *slot;
    int2 *edge; int4 *xh, *hh0, *hh1;
    cudaGetSymbolAddress((void**)&deg,   g_deg);
    cudaGetSymbolAddress((void**)&off,   g_off);
    cudaGetSymbolAddress((void**)&bsums, g_bsums);
    cudaGetSymbolAddress((void**)&slot,  g_slot);
    cudaGetSymbolAddress((void**)&edge,  g_edge);
    cudaGetSymbolAddress((void**)&xh,    g_xh);
    cudaGetSymbolAddress((void**)&hh0,   g_hh0);
    cudaGetSymbolAddress((void**)&hh1,   g_hh1);

    const float4* x4 = (const float4*)x;
    int nb  = (N + 1023) / 1024;
    int ni4 = N * NI4;

    k_detect<<<1, 256>>>((const int*)ei, E);
    k_zero<<<(N + 255) / 256, 256>>>(deg, N);
    k_xhalf<<<(ni4 + 255) / 256, 256>>>(x4, xh, ni4);
    k_narrow<<<((E + 7) / 8 + 255) / 256, 256>>>(ei, deg, slot, E, N);
    k_scan1<<<nb, 1024>>>(deg, off, bsums, N);
    k_scan2<<<1, 32>>>(bsums, nb);
    k_scan3<<<nb, 1024>>>(off, bsums, N, E);
    k_scatter<<<((E + 3) / 4 + 255) / 256, 256>>>(ei, slot, ew, off, edge, E, N);

    int pblocks = (N * 8 + 255) / 256;
    const int4* src = xh;
    for (int k = 0; k < KITER; k++) {
        if (k == KITER - 1) {
            k_proph<true><<<pblocks, 256>>>(src, xh, x4, nullptr, (float4*)d_out,
                                            off, edge, N);
        } else {
            int4* dst = ((k & 1) == 0) ? hh0 : hh1;
            k_proph<false><<<pblocks, 256>>>(src, xh, x4, dst, nullptr,
                                             off, edge, N);
            src = dst;
        }
    }
}